// round 5
// baseline (speedup 1.0000x reference)
#include <cuda_runtime.h>
#include <math.h>

#define NQ   32
#define MM   32
#define ND_  200
#define NN   160
#define HH   768
#define DIMV 128
#define NEGV (-10000.0f)

typedef unsigned long long ull;

// Packed dual-FMA: d.lo += a.lo*b.lo ; d.hi += a.hi*b.hi  (sm_100+ only).
// This is the ONLY way to reach the full 128 FP32 lanes/SM on B300:
// scalar FFMA (3-reg) issues at rt_SMSP=2 (half rate).
#define FMA2(acc, a, b) \
    asm("fma.rn.f32x2 %0, %1, %2, %0;" : "+l"(acc) : "l"(a), "l"(b))

// Scratch (no cudaMalloc allowed): projected+normalized embeddings.
__device__ float g_Qp[NQ * MM * DIMV];     // 0.5 MB
__device__ float g_Dp[ND_ * NN * DIMV];    // 16.4 MB (L2-resident)

// ---------------------------------------------------------------------------
// Combined projection + row L2-normalize for BOTH Q and D in one launch.
// Block bx<16 -> Q rows, else D rows. 64 rows x 128 cols per block.
// Thread tile: 8m x 4n. mg = warp (8 rows), ng = lane (n = ng + 32j).
// W is staged k-transposed in smem with XOR swizzle slot = k ^ ((n&15)<<1)
// so that (k,k+1) 8-byte loads are phase-conflict-free for lanes ng=0..31.
// ---------------------------------------------------------------------------
__global__ __launch_bounds__(256, 2) void proj_kernel(
    const float* __restrict__ Qx, const float* __restrict__ Dx,
    const float* __restrict__ W,
    float* __restrict__ Qy, float* __restrict__ Dy)
{
    __shared__ __align__(16) float Xs[64][34];      // 8.7 KB (even pad -> .64 ok)
    __shared__ __align__(16) float Wt[128 * 32];    // 16 KB, swizzled

    const int bx = blockIdx.x;
    const float* X; float* Y; size_t row0;
    if (bx < 16) { X = Qx; Y = Qy; row0 = (size_t)bx * 64; }
    else         { X = Dx; Y = Dy; row0 = (size_t)(bx - 16) * 64; }

    const int tid = threadIdx.x;
    const int mg  = tid >> 5;        // warp id -> rows mg*8 .. mg*8+7
    const int ng  = tid & 31;        // lane   -> cols ng + 32j

    ull acc2[8][4];
#pragma unroll
    for (int i = 0; i < 8; i++)
#pragma unroll
        for (int j = 0; j < 4; j++) acc2[i][j] = 0ull;   // (0.f,0.f)

    for (int kt = 0; kt < HH; kt += 32) {
        // Xs: 64x32, coalesced, conflict-free writes (stride 34).
#pragma unroll
        for (int t = 0; t < 8; t++) {
            int idx = tid + 256 * t;
            int r = idx >> 5, k = idx & 31;
            Xs[r][k] = X[(row0 + r) * HH + kt + k];
        }
        // Wt: k-transposed + swizzled. gmem reads coalesced over n.
#pragma unroll
        for (int t = 0; t < 16; t++) {
            int idx = tid + 256 * t;
            int k = idx >> 7, n = idx & 127;
            Wt[n * 32 + (k ^ ((n & 15) << 1))] = W[(size_t)(kt + k) * DIMV + n];
        }
        __syncthreads();

#pragma unroll 4
        for (int k = 0; k < 32; k += 2) {
            ull a2[8], b2[4];
#pragma unroll
            for (int i = 0; i < 8; i++)
                a2[i] = *(const ull*)&Xs[mg * 8 + i][k];    // warp broadcast
#pragma unroll
            for (int j = 0; j < 4; j++) {
                int n = ng + 32 * j;
                b2[j] = *(const ull*)&Wt[n * 32 + (k ^ ((n & 15) << 1))];
            }
#pragma unroll
            for (int i = 0; i < 8; i++)
#pragma unroll
                for (int j = 0; j < 4; j++) FMA2(acc2[i][j], a2[i], b2[j]);
        }
        __syncthreads();
    }

    // Row L2 norm: full warp owns each row's 128 cols -> shfl reduce.
#pragma unroll
    for (int i = 0; i < 8; i++) {
        float y[4], ss = 0.0f;
#pragma unroll
        for (int j = 0; j < 4; j++) {
            float lo, hi;
            asm("mov.b64 {%0,%1}, %2;" : "=f"(lo), "=f"(hi) : "l"(acc2[i][j]));
            y[j] = lo + hi;
            ss += y[j] * y[j];
        }
#pragma unroll
        for (int off = 16; off >= 1; off >>= 1)
            ss += __shfl_xor_sync(0xffffffffu, ss, off);
        float inv = 1.0f / fmaxf(sqrtf(ss), 1e-12f);
        size_t r = row0 + mg * 8 + i;
#pragma unroll
        for (int j = 0; j < 4; j++)
            Y[r * DIMV + ng + 32 * j] = y[j] * inv;
    }
}

// ---------------------------------------------------------------------------
// Fused scoring kernel: one block per (q,d). 128 threads (4 warps),
// 2 blocks co-resident per SM (smem 100.4 KB each).
//   sim = Qp[q] (32x128) @ Dp[d]^T (160x128), packed f32x2 FMA
//   n* = argmax_n (sim_masked*10 + gumbel);  out = sum_m qmask * s[m,n*]
// Warp = 8 m-rows (m = warp*8+i), lane owns n = lane*5+j.
// Dp stride 130 (even): lane stride 650 floats -> per-phase banks 10*l mod 32
// all distinct -> conflict-free LDS.64.
// ---------------------------------------------------------------------------
#define DPS 130
__global__ __launch_bounds__(128) void score_kernel(
    const float* __restrict__ gumbel,
    const float* __restrict__ q_mask,
    const float* __restrict__ d_mask,
    float* __restrict__ out)
{
    extern __shared__ float smem[];
    float* Dp_s    = smem;                    // [160][130]
    float* Qp_s    = Dp_s + NN * DPS;         // [32][128]
    float* dmask_s = Qp_s + MM * DIMV;        // [160]
    float* qmask_s = dmask_s + NN;            // [32]
    float* partial = qmask_s + MM;            // [4]

    const int bx   = blockIdx.x;              // q*200 + d
    const int d    = bx % ND_;
    const int q    = bx / ND_;
    const int tid  = threadIdx.x;
    const int warp = tid >> 5;                // 0..3 -> 8 m rows each
    const int lane = tid & 31;                // -> 5 n each

    // Load Dp[d]: 160x128 = 5120 float4, 40 per thread (L2-resident source).
    {
        const float4* Dg = (const float4*)(g_Dp + (size_t)d * NN * DIMV);
#pragma unroll
        for (int it = 0; it < 40; it++) {
            int idx4 = tid + 128 * it;
            int n = idx4 >> 5, k4 = idx4 & 31;
            float4 v = Dg[idx4];
            float* dst = Dp_s + n * DPS + k4 * 4;
            dst[0] = v.x; dst[1] = v.y; dst[2] = v.z; dst[3] = v.w;
        }
    }
    // Load Qp[q]: 1024 float4, 8 per thread.
    {
        const float4* Qg = (const float4*)(g_Qp + (size_t)q * MM * DIMV);
#pragma unroll
        for (int it = 0; it < 8; it++) {
            int idx4 = tid + 128 * it;
            float4 v = Qg[idx4];
            float* dst = Qp_s + idx4 * 4;
            dst[0] = v.x; dst[1] = v.y; dst[2] = v.z; dst[3] = v.w;
        }
    }
    for (int i = tid; i < NN; i += 128) dmask_s[i] = d_mask[(size_t)d * NN + i];
    if (tid < MM) qmask_s[tid] = q_mask[(size_t)q * MM + tid];
    __syncthreads();

    // 8m x 5n register tile, packed f32x2 over k-pairs.
    ull acc2[8][5];
#pragma unroll
    for (int i = 0; i < 8; i++)
#pragma unroll
        for (int j = 0; j < 5; j++) acc2[i][j] = 0ull;

    const float* Qrow = Qp_s + (warp * 8) * DIMV;
    const float* Drow = Dp_s + (lane * 5) * DPS;

#pragma unroll 2
    for (int k = 0; k < DIMV; k += 2) {
        ull a2[8], b2[5];
#pragma unroll
        for (int i = 0; i < 8; i++)
            a2[i] = *(const ull*)&Qrow[i * DIMV + k];      // warp broadcast
#pragma unroll
        for (int j = 0; j < 5; j++)
            b2[j] = *(const ull*)&Drow[j * DPS + k];       // conflict-free
#pragma unroll
        for (int i = 0; i < 8; i++)
#pragma unroll
            for (int j = 0; j < 5; j++) FMA2(acc2[i][j], a2[i], b2[j]);
    }

    // Epilogue: unpack, mask, gumbel-argmax per m, weighted sum.
    const float* gb = gumbel + (size_t)bx * MM * NN;
    float psum = 0.0f;
#pragma unroll
    for (int i = 0; i < 8; i++) {
        const int m = warp * 8 + i;
        float bestz = -3.0e38f, bests = 0.0f;
#pragma unroll
        for (int j = 0; j < 5; j++) {
            const int n = lane * 5 + j;
            float lo, hi;
            asm("mov.b64 {%0,%1}, %2;" : "=f"(lo), "=f"(hi) : "l"(acc2[i][j]));
            float sim = lo + hi;
            float dm = dmask_s[n];
            float sv = sim * dm + (1.0f - dm) * NEGV;      // exact select
            float z  = sv * 10.0f + gb[m * NN + n];        // TEMP=0.1
            if (z > bestz) { bestz = z; bests = sv; }
        }
#pragma unroll
        for (int off = 16; off >= 1; off >>= 1) {
            float zo = __shfl_xor_sync(0xffffffffu, bestz, off);
            float so = __shfl_xor_sync(0xffffffffu, bests, off);
            if (zo > bestz) { bestz = zo; bests = so; }
        }
        psum += qmask_s[m] * bests;
    }
    if (lane == 0) partial[warp] = psum;
    __syncthreads();
    if (tid == 0)
        out[bx] = (partial[0] + partial[1]) + (partial[2] + partial[3]);
}

// ---------------------------------------------------------------------------
extern "C" void kernel_launch(void* const* d_in, const int* in_sizes, int n_in,
                              void* d_out, int out_size)
{
    const float* Q      = (const float*)d_in[0];  // (32,32,768)
    const float* D      = (const float*)d_in[1];  // (200,160,768)
    const float* q_mask = (const float*)d_in[2];  // (32,32)
    const float* d_mask = (const float*)d_in[3];  // (200,160)
    const float* gumbel = (const float*)d_in[4];  // (32,200,32,160)
    const float* W      = (const float*)d_in[5];  // (768,128)
    float* out = (float*)d_out;                   // (32,200)

    float* Qp; cudaGetSymbolAddress((void**)&Qp, g_Qp);
    float* Dp; cudaGetSymbolAddress((void**)&Dp, g_Dp);

    // One combined projection launch: 16 Q-blocks + 500 D-blocks.
    proj_kernel<<<516, 256>>>(Q, D, W, Qp, Dp);

    // Fused sim + gumbel-argmax + score. 100.4 KB smem -> 2 blocks/SM.
    const int smem_bytes = (NN * DPS + MM * DIMV + NN + MM + 4) * sizeof(float);
    cudaFuncSetAttribute(score_kernel,
                         cudaFuncAttributeMaxDynamicSharedMemorySize, smem_bytes);
    score_kernel<<<NQ * ND_, 128, smem_bytes>>>(gumbel, q_mask, d_mask, out);
}

// round 8
// speedup vs baseline: 1.5721x; 1.5721x over previous
#include <cuda_runtime.h>
#include <math.h>

#define NQ   32
#define MM   32
#define ND_  200
#define NN   160
#define HH   768
#define DIMV 128
#define NEGV (-10000.0f)

typedef unsigned long long ull;

// Packed dual-FMA (sm_100+): acc.lo += a.lo*b.lo ; acc.hi += a.hi*b.hi.
// Scalar FFMA issues at rt_SMSP=2 (half the FP32 lanes); f32x2 doubles it.
#define FMA2(acc, a, b) \
    asm("fma.rn.f32x2 %0, %1, %2, %0;" : "+l"(acc) : "l"(a), "l"(b))

// Scratch (no cudaMalloc allowed): projected+normalized embeddings.
__device__ float g_Qp[NQ * MM * DIMV];     // 0.5 MB
__device__ float g_Dp[ND_ * NN * DIMV];    // 16.4 MB (stays L2-resident)

// ---------------------------------------------------------------------------
// Projection + row L2-normalize for BOTH Q and D in one launch.
// 258 blocks x 512 threads; block = 128 rows x 128 cols. bx<8 -> Q else D.
// Warp tile: 8m x 128n (lane n = lane + 32j, j<4). f32x2 over k-pairs.
// W staged pair-interleaved: Wp[(k>>1)*258 + 2n + (k&1)] -> 8B reads give
// (W[k][n],W[k+1][n]); 32 lanes x 8B contiguous = two conflict-free
// 128B LDS.64 phases.
// ---------------------------------------------------------------------------
__global__ __launch_bounds__(512) void proj_kernel(
    const float* __restrict__ Qx, const float* __restrict__ Dx,
    const float* __restrict__ W,
    float* __restrict__ Qy, float* __restrict__ Dy)
{
    __shared__ __align__(16) float Xs[128 * 36];    // stride 36 (mult of 4)
    __shared__ __align__(16) float Wp[16 * 258];    // 16 k-pairs x 128n pairs

    const int bx = blockIdx.x;
    const float* X; float* Y; size_t row0;
    if (bx < 8) { X = Qx; Y = Qy; row0 = (size_t)bx * 128; }
    else        { X = Dx; Y = Dy; row0 = (size_t)(bx - 8) * 128; }

    const int tid  = threadIdx.x;
    const int warp = tid >> 5;       // 0..15 -> rows warp*8 .. +7
    const int lane = tid & 31;       // -> cols lane + 32j

    ull acc2[8][4];
#pragma unroll
    for (int i = 0; i < 8; i++)
#pragma unroll
        for (int j = 0; j < 4; j++) acc2[i][j] = 0ull;

    for (int kt = 0; kt < HH; kt += 32) {
        // Xs: 128 rows x 32 k, coalesced (one warp row-chunk per iteration).
#pragma unroll
        for (int t = 0; t < 8; t++) {
            int idx = tid + 512 * t;
            int r = idx >> 5, k = idx & 31;
            Xs[r * 36 + k] = X[(row0 + r) * HH + kt + k];
        }
        // Wp: pair-interleaved, gmem coalesced over n.
#pragma unroll
        for (int t = 0; t < 8; t++) {
            int idx = tid + 512 * t;
            int k = idx >> 7, n = idx & 127;
            Wp[(k >> 1) * 258 + 2 * n + (k & 1)] =
                W[(size_t)(kt + k) * DIMV + n];
        }
        __syncthreads();

#pragma unroll 4
        for (int k = 0; k < 32; k += 2) {
            ull a2[8], b2[4];
#pragma unroll
            for (int i = 0; i < 8; i++)
                a2[i] = *(const ull*)&Xs[(warp * 8 + i) * 36 + k]; // broadcast
#pragma unroll
            for (int j = 0; j < 4; j++)
                b2[j] = *(const ull*)&Wp[(k >> 1) * 258 + 2 * (lane + 32 * j)];
#pragma unroll
            for (int i = 0; i < 8; i++)
#pragma unroll
                for (int j = 0; j < 4; j++) FMA2(acc2[i][j], a2[i], b2[j]);
        }
        __syncthreads();
    }

    // Row L2 norm: full warp owns each row's 128 cols -> shfl reduce.
#pragma unroll
    for (int i = 0; i < 8; i++) {
        float y[4], ss = 0.0f;
#pragma unroll
        for (int j = 0; j < 4; j++) {
            float lo, hi;
            asm("mov.b64 {%0,%1}, %2;" : "=f"(lo), "=f"(hi) : "l"(acc2[i][j]));
            y[j] = lo + hi;
            ss += y[j] * y[j];
        }
#pragma unroll
        for (int off = 16; off >= 1; off >>= 1)
            ss += __shfl_xor_sync(0xffffffffu, ss, off);
        float inv = 1.0f / fmaxf(sqrtf(ss), 1e-12f);
        size_t r = row0 + warp * 8 + i;
#pragma unroll
        for (int j = 0; j < 4; j++)
            Y[r * DIMV + lane + 32 * j] = y[j] * inv;
    }
}

// ---------------------------------------------------------------------------
// Fused scoring kernel: one block per (q,d). 256 threads (8 warps),
// 2 blocks/SM (smem ~99 KB each) -> 16 warps/SM.
// Warp tile: 8m x 80n. warp w: mg=w>>1 (rows mg*8..+7), nh=w&1 (n base nh*80).
// lane: lh=lane>>4 -> m-sub (4 rows), ln=lane&15 -> n-group of 5.
// Lanes l and l+16 read the SAME Dp word (broadcast pair) -> b-loads 1 cyc;
// Qp pad 132 puts the two a-addresses (rows +0/+4) in different banks.
// DPS=130: 10*ln mod 32 is a 16-element permutation -> conflict-free.
// ---------------------------------------------------------------------------
#define DPS 130
#define QPS 132
__global__ __launch_bounds__(256, 2) void score_kernel(
    const float* __restrict__ gumbel,
    const float* __restrict__ q_mask,
    const float* __restrict__ d_mask,
    float* __restrict__ out)
{
    extern __shared__ float smem[];
    float* Dp_s    = smem;                    // [160][130]
    float* Qp_s    = Dp_s + NN * DPS;         // [32][132]
    float* dmask_s = Qp_s + MM * QPS;         // [160]
    float* qmask_s = dmask_s + NN;            // [32]
    float* zbuf    = qmask_s + MM;            // [32][2]
    float* sbuf    = zbuf + 64;               // [32][2]

    const int bx   = blockIdx.x;              // q*200 + d
    const int d    = bx % ND_;
    const int q    = bx / ND_;
    const int tid  = threadIdx.x;
    const int warp = tid >> 5;                // 0..7
    const int lane = tid & 31;
    const int mg   = warp >> 1;               // 0..3
    const int nh   = warp & 1;                // 0..1
    const int lh   = lane >> 4;               // 0..1
    const int ln   = lane & 15;               // 0..15

    // Load Dp[d]: 160x128 floats as 10240 float2, 40 per thread (L2 source).
    {
        const float2* Dg = (const float2*)(g_Dp + (size_t)d * NN * DIMV);
#pragma unroll
        for (int it = 0; it < 40; it++) {
            int idx2 = tid + 256 * it;
            int n = idx2 >> 6, k2 = idx2 & 63;
            *(float2*)&Dp_s[n * DPS + 2 * k2] = Dg[idx2];
        }
    }
    // Load Qp[q]: 1024 float4, 4 per thread (row stride 132, 16B-aligned).
    {
        const float4* Qg = (const float4*)(g_Qp + (size_t)q * MM * DIMV);
#pragma unroll
        for (int it = 0; it < 4; it++) {
            int idx4 = tid + 256 * it;
            int m = idx4 >> 5, k4 = idx4 & 31;
            *(float4*)&Qp_s[m * QPS + 4 * k4] = Qg[idx4];
        }
    }
    if (tid < NN) dmask_s[tid] = d_mask[(size_t)d * NN + tid];
    if (tid < MM) qmask_s[tid] = q_mask[(size_t)q * MM + tid];
    __syncthreads();

    // 4m x 5n register tile, packed f32x2 over k-pairs.
    ull acc2[4][5];
#pragma unroll
    for (int i = 0; i < 4; i++)
#pragma unroll
        for (int j = 0; j < 5; j++) acc2[i][j] = 0ull;

    const float* Qrow = Qp_s + (mg * 8 + lh * 4) * QPS;
    const float* Drow = Dp_s + (nh * 80 + ln * 5) * DPS;

#pragma unroll 4
    for (int k = 0; k < DIMV; k += 2) {
        ull a2[4], b2[5];
#pragma unroll
        for (int i = 0; i < 4; i++)
            a2[i] = *(const ull*)&Qrow[i * QPS + k];   // 2 addrs, diff banks
#pragma unroll
        for (int j = 0; j < 5; j++)
            b2[j] = *(const ull*)&Drow[j * DPS + k];   // bcast pairs, CF
#pragma unroll
        for (int i = 0; i < 4; i++)
#pragma unroll
            for (int j = 0; j < 5; j++) FMA2(acc2[i][j], a2[i], b2[j]);
    }

    // Epilogue: mask, gumbel-argmax over this warp's 80 n per row, then
    // combine the two n-halves via smem.
    const float* gb = gumbel + (size_t)bx * MM * NN;
#pragma unroll
    for (int i = 0; i < 4; i++) {
        const int m = mg * 8 + lh * 4 + i;
        float bestz = -3.0e38f, bests = 0.0f;
#pragma unroll
        for (int j = 0; j < 5; j++) {
            const int n = nh * 80 + ln * 5 + j;
            float lo, hi;
            asm("mov.b64 {%0,%1}, %2;" : "=f"(lo), "=f"(hi) : "l"(acc2[i][j]));
            float sim = lo + hi;
            float dm = dmask_s[n];
            float sv = sim * dm + (1.0f - dm) * NEGV;     // exact select
            float z  = sv * 10.0f + gb[m * NN + n];       // TEMP=0.1
            if (z > bestz) { bestz = z; bests = sv; }
        }
        // reduce within the 16-lane group (xor of low 4 bits keeps lh group)
#pragma unroll
        for (int off = 8; off >= 1; off >>= 1) {
            float zo = __shfl_xor_sync(0xffffffffu, bestz, off);
            float so = __shfl_xor_sync(0xffffffffu, bests, off);
            if (zo > bestz) { bestz = zo; bests = so; }
        }
        if (ln == 0) { zbuf[m * 2 + nh] = bestz; sbuf[m * 2 + nh] = bests; }
    }
    __syncthreads();

    if (warp == 0) {
        const int m = lane;
        float z0 = zbuf[2 * m], z1 = zbuf[2 * m + 1];
        float s  = (z1 > z0) ? sbuf[2 * m + 1] : sbuf[2 * m];
        float p  = qmask_s[m] * s;
#pragma unroll
        for (int off = 16; off >= 1; off >>= 1)
            p += __shfl_xor_sync(0xffffffffu, p, off);
        if (lane == 0) out[bx] = p;
    }
}

// ---------------------------------------------------------------------------
extern "C" void kernel_launch(void* const* d_in, const int* in_sizes, int n_in,
                              void* d_out, int out_size)
{
    const float* Q      = (const float*)d_in[0];  // (32,32,768)
    const float* D      = (const float*)d_in[1];  // (200,160,768)
    const float* q_mask = (const float*)d_in[2];  // (32,32)
    const float* d_mask = (const float*)d_in[3];  // (200,160)
    const float* gumbel = (const float*)d_in[4];  // (32,200,32,160)
    const float* W      = (const float*)d_in[5];  // (768,128)
    float* out = (float*)d_out;                   // (32,200)

    float* Qp; cudaGetSymbolAddress((void**)&Qp, g_Qp);
    float* Dp; cudaGetSymbolAddress((void**)&Dp, g_Dp);

    // Combined projection: 8 Q-blocks + 250 D-blocks of 128 rows each.
    proj_kernel<<<258, 512>>>(Q, D, W, Qp, Dp);

    // Fused sim + gumbel-argmax + score. ~99 KB smem -> 2 blocks/SM.
    const int smem_bytes =
        (NN * DPS + MM * QPS + NN + MM + 64 + 64) * sizeof(float);
    cudaFuncSetAttribute(score_kernel,
                         cudaFuncAttributeMaxDynamicSharedMemorySize, smem_bytes);
    score_kernel<<<NQ * ND_, 256, smem_bytes>>>(gumbel, q_mask, d_mask, out);
}